// round 9
// baseline (speedup 1.0000x reference)
#include <cuda_runtime.h>
#include <cstdint>
#include <cfloat>

// Problem constants (fixed by the dataset)
constexpr int Bv  = 16;      // batch
constexpr int Nv  = 16384;   // pixels
constexpr int Dv  = 64;      // embed dim
constexpr int Kv  = 64;      // templates
constexpr int D4v = Dv / 4;  // float4 chunks per vector (16)
constexpr int PPB = 4;       // pixels per block = warps per block (1 warp : 1 pixel)
constexpr float EPS = 1e-3f; // near-tie margin (>> fp32 dist error ~1e-5)

using ull = unsigned long long;

// Swizzles (verified conflict-free per 8-lane phase for staging, norms, and
// the main loop's k = r + 8j / b = c + 4i access octets).
__device__ __forceinline__ int tsw(int k, int d4) {
    return k * 16 + (d4 ^ (k & 7) ^ (k >> 3));
}
__device__ __forceinline__ int xsw(int b, int d4) {
    return b * 16 + (d4 ^ (b & 7));
}

struct Pix {                      // per-pixel smem region (21120 B, 16B aligned)
    float4 ts[Kv * 16];           // 16384 B template tile (swizzled)
    float4 xs[Bv * 16];           //  4096 B frame tile (swizzled)
    float  t2s[Kv];
    float  x2s[Bv];
    float  bestv[Bv];
    int    bestk[Bv];
    int    cnt[Bv];
    ull    refined[Bv];
};
constexpr int SMEM_BYTES = (int)(PPB * sizeof(Pix)) + 4 * Bv * PPB * (int)sizeof(float);

__global__ __launch_bounds__(128, 2)
void osc_kernel(const float4* __restrict__ xg,     // frame_embeddings [B,N,D] f32
                const float4* __restrict__ tg,     // templates        [K,N,D] f32
                const int*    __restrict__ tcls,   // template_classes [K] int32
                float* __restrict__ out)
{
    extern __shared__ char smem_raw[];
    Pix*   pix  = reinterpret_cast<Pix*>(smem_raw);
    float* obuf = reinterpret_cast<float*>(smem_raw + PPB * sizeof(Pix)); // [4][16][PPB]

    const int tid  = threadIdx.x;
    const int w    = tid >> 5;           // warp id = pixel slot
    const int lane = tid & 31;
    const int n0   = blockIdx.x * PPB;
    const int n    = n0 + w;
    Pix& P = pix[w];

    // ---- stage template tile: 32 float4/lane, coalesced 2x256B per instr ----
#pragma unroll
    for (int i = 0; i < 32; ++i) {
        int idx = lane + i * 32;
        int k   = idx >> 4;
        int d4  = idx & 15;
        P.ts[tsw(k, d4)] = tg[((size_t)k * Nv + n) * D4v + d4];
    }
    // ---- stage frame tile: 8 float4/lane ----
#pragma unroll
    for (int i = 0; i < 8; ++i) {
        int idx = lane + i * 32;
        int b   = idx >> 4;
        int d4  = idx & 15;
        P.xs[xsw(b, d4)] = xg[((size_t)b * Nv + n) * D4v + d4];
    }
    if (lane < Bv) {
        P.cnt[lane]     = 0;
        P.refined[lane] = 0xFFFFFFFFFFFFFFFFULL;
    }
    __syncwarp();

    // ---- norms: each lane 2 template rows; lanes<16 one x row ----
#pragma unroll
    for (int rr = 0; rr < 2; ++rr) {
        const int k = lane + 32 * rr;
        float s0 = 0.f, s1 = 0.f, s2 = 0.f, s3 = 0.f;
#pragma unroll
        for (int d4 = 0; d4 < D4v; ++d4) {
            float4 v = P.ts[tsw(k, d4)];
            s0 = fmaf(v.x, v.x, s0); s1 = fmaf(v.y, v.y, s1);
            s2 = fmaf(v.z, v.z, s2); s3 = fmaf(v.w, v.w, s3);
        }
        P.t2s[k] = (s0 + s1) + (s2 + s3);
    }
    if (lane < Bv) {
        float s0 = 0.f, s1 = 0.f, s2 = 0.f, s3 = 0.f;
#pragma unroll
        for (int d4 = 0; d4 < D4v; ++d4) {
            float4 v = P.xs[xsw(lane, d4)];
            s0 = fmaf(v.x, v.x, s0); s1 = fmaf(v.y, v.y, s1);
            s2 = fmaf(v.z, v.z, s2); s3 = fmaf(v.w, v.w, s3);
        }
        P.x2s[lane] = (s0 + s1) + (s2 + s3);
    }
    __syncwarp();

    // ---- Phase A: 4b x 8k register tile; one warp covers 16b x 64k ----
    // lane: c = lane&3 -> b in {c, c+4, c+8, c+12}; r = lane>>2 -> k = r + 8j
    const int c = lane & 3;
    const int r = lane >> 2;

    float acc[4][8];
#pragma unroll
    for (int i = 0; i < 4; ++i)
#pragma unroll
        for (int j = 0; j < 8; ++j) acc[i][j] = 0.f;

#pragma unroll 4
    for (int d4 = 0; d4 < D4v; ++d4) {
        float4 xv[4], tv[8];
#pragma unroll
        for (int i = 0; i < 4; ++i) xv[i] = P.xs[xsw(c + 4 * i, d4)];   // 4 distinct/warp
#pragma unroll
        for (int j = 0; j < 8; ++j) tv[j] = P.ts[tsw(r + 8 * j, d4)];   // 8 distinct/warp
#pragma unroll
        for (int i = 0; i < 4; ++i)
#pragma unroll
            for (int j = 0; j < 8; ++j) {
                acc[i][j] = fmaf(xv[i].x, tv[j].x, acc[i][j]);
                acc[i][j] = fmaf(xv[i].y, tv[j].y, acc[i][j]);
                acc[i][j] = fmaf(xv[i].z, tv[j].z, acc[i][j]);
                acc[i][j] = fmaf(xv[i].w, tv[j].w, acc[i][j]);
            }
    }

    // ---- distances + per-thread min over its 8 k's per b ----
    float df[4][8];
    float bv[4];
    int   bk[4];
#pragma unroll
    for (int i = 0; i < 4; ++i) {
        const float bx2 = P.x2s[c + 4 * i];
        bv[i] = FLT_MAX; bk[i] = Kv;
#pragma unroll
        for (int j = 0; j < 8; ++j) {
            const int k = r + 8 * j;
            const float d = bx2 + P.t2s[k] - 2.0f * acc[i][j];
            df[i][j] = d;
            if (d < bv[i]) { bv[i] = d; bk[i] = k; }  // j asc == k asc: first-min
        }
    }

    // ---- shuffle reduce across the 8 r-groups (lanes with same c) ----
#pragma unroll
    for (int m = 4; m <= 16; m <<= 1) {
#pragma unroll
        for (int i = 0; i < 4; ++i) {
            const float ov = __shfl_xor_sync(0xFFFFFFFFu, bv[i], m);
            const int   ok = __shfl_xor_sync(0xFFFFFFFFu, bk[i], m);
            if (ov < bv[i] || (ov == bv[i] && ok < bk[i])) { bv[i] = ov; bk[i] = ok; }
        }
    }
    if (r == 0) {
#pragma unroll
        for (int i = 0; i < 4; ++i) {
            P.bestv[c + 4 * i] = bv[i];
            P.bestk[c + 4 * i] = bk[i];
        }
    }
    __syncwarp();

    // ---- near-tie candidate count per b ----
#pragma unroll
    for (int i = 0; i < 4; ++i) {
        const int b = c + 4 * i;
        const float lim = P.bestv[b] + EPS;
        int local = 0;
#pragma unroll
        for (int j = 0; j < 8; ++j) local += (df[i][j] <= lim) ? 1 : 0;
        if (local) atomicAdd(&P.cnt[b], local);
    }
    __syncwarp();

    // ---- Phase B (RARE): exact fp64 refinement for contested b ----
#pragma unroll
    for (int i = 0; i < 4; ++i) {
        const int b = c + 4 * i;
        if (P.cnt[b] < 2) continue;                  // uncontested: skip fp64
        const float lim = P.bestv[b] + EPS;
#pragma unroll
        for (int j = 0; j < 8; ++j) {
            if (df[i][j] > lim) continue;
            const int k = r + 8 * j;
            double dd = 0.0;
            for (int d4 = 0; d4 < D4v; ++d4) {
                const float4 xv = P.xs[xsw(b, d4)];
                const float4 tv = P.ts[tsw(k, d4)];
                const double e0 = (double)xv.x - (double)tv.x;
                const double e1 = (double)xv.y - (double)tv.y;
                const double e2 = (double)xv.z - (double)tv.z;
                const double e3 = (double)xv.w - (double)tv.w;
                dd = fma(e0, e0, dd);
                dd = fma(e1, e1, dd);
                dd = fma(e2, e2, dd);
                dd = fma(e3, e3, dd);
            }
            const float dfx = (float)dd;             // exact -> fp32
            const ull key = ((ull)__float_as_uint(dfx) << 6) | (ull)k;
            atomicMin(&P.refined[b], key);
        }
    }
    __syncwarp();

    // ---- per-b finalize into obuf[o][b][w] ----
    if (lane < Bv) {
        float fbv;
        int   fbk;
        if (P.cnt[lane] >= 2) {
            const ull key = P.refined[lane];
            fbk = (int)(key & 63ULL);
            fbv = __uint_as_float((unsigned int)(key >> 6));
        } else {
            fbv = P.bestv[lane];
            fbk = P.bestk[lane];
        }
        obuf[(0 * Bv + lane) * PPB + w] = (fbv <= 0.5f) ? 1.0f : 0.0f;
        obuf[(1 * Bv + lane) * PPB + w] = (fbv <= 1.0f) ? 1.0f : 0.0f;
        obuf[(2 * Bv + lane) * PPB + w] = fbv;
        obuf[(3 * Bv + lane) * PPB + w] = (float)__ldg(&tcls[fbk]);
    }
    __syncthreads();

    // ---- block epilogue: 64 threads each store one float4 (4 pixels wide) ----
    if (tid < 4 * Bv) {
        const int o = tid >> 4;
        const int b = tid & 15;
        const size_t BN = (size_t)Bv * Nv;
        const float4 v = *reinterpret_cast<const float4*>(&obuf[(o * Bv + b) * PPB]);
        *reinterpret_cast<float4*>(&out[(size_t)o * BN + (size_t)b * Nv + n0]) = v;
    }
}

extern "C" void kernel_launch(void* const* d_in, const int* in_sizes, int n_in,
                              void* d_out, int out_size)
{
    const float4* frame = (const float4*)d_in[0];   // [16,16384,64] f32
    const float4* tmpl  = (const float4*)d_in[1];   // [64,16384,64] f32
    const int*    tcls  = (const int*)d_in[2];      // [64] int32
    float*        out   = (float*)d_out;

    cudaFuncSetAttribute(osc_kernel,
                         cudaFuncAttributeMaxDynamicSharedMemorySize, SMEM_BYTES);
    osc_kernel<<<Nv / PPB, 32 * PPB, SMEM_BYTES>>>(frame, tmpl, tcls, out);
}

// round 10
// speedup vs baseline: 1.3225x; 1.3225x over previous
#include <cuda_runtime.h>
#include <cstdint>
#include <cfloat>

// Problem constants (fixed by the dataset)
constexpr int Bv  = 16;      // batch
constexpr int Nv  = 16384;   // pixels
constexpr int Dv  = 64;      // embed dim
constexpr int Kv  = 64;      // templates
constexpr int D4v = Dv / 4;  // float4 chunks per vector (16)
constexpr int PPB = 2;       // pixels per block (warp-pair each -> all 4 SMSPs)
constexpr float EPS = 1e-3f; // near-tie margin (>> fp32 dist error ~1e-5)

using ull = unsigned long long;

// ---- packed f32x2 helpers (sm_103a; per-lane rounding identical to fmaf) ----
__device__ __forceinline__ ull f2_fma(ull a, ull b, ull c) {
    ull d;
    asm("fma.rn.f32x2 %0, %1, %2, %3;" : "=l"(d) : "l"(a), "l"(b), "l"(c));
    return d;
}
__device__ __forceinline__ void f2_unpack(ull p, float& lo, float& hi) {
    unsigned a, b;
    asm("mov.b64 {%0, %1}, %2;" : "=r"(a), "=r"(b) : "l"(p));
    lo = __uint_as_float(a); hi = __uint_as_float(b);
}

// XOR swizzle (conflict-free per 8-lane phase for all our access patterns)
__device__ __forceinline__ int tsw(int k, int d4) { return k * 16 + (d4 ^ (k & 7)); }
__device__ __forceinline__ int xsw(int b, int d4) { return b * 16 + (d4 ^ (b & 7)); }

__global__ __launch_bounds__(128)
void osc_kernel(const float4* __restrict__ xg,     // frame_embeddings [B,N,D] f32
                const float4* __restrict__ tg,     // templates        [K,N,D] f32
                const int*    __restrict__ tcls,   // template_classes [K] int32
                float* __restrict__ out)
{
    __shared__ __align__(16) float4 ts[PPB][Kv * 16];  // template tiles (swizzled)
    __shared__ __align__(16) float4 xs[PPB][Bv * 16];  // frame tiles (swizzled)
    __shared__ float t2s[PPB][Kv];
    __shared__ float x2s[PPB][Bv];
    __shared__ float clsf[Kv];
    __shared__ float rv[PPB][Bv][17];                  // pitch 17: conflict-free scan
    __shared__ int   ri[PPB][Bv][17];
    __shared__ float bestvs[PPB][Bv];
    __shared__ int   bestks[PPB][Bv];
    __shared__ int   cnt[PPB][Bv];
    __shared__ ull   refined[PPB][Bv];

    const int tid = threadIdx.x;
    const int p   = tid >> 6;            // pixel slot 0/1 (warps 0,1 | 2,3)
    const int q   = tid & 63;            // thread id within pixel
    const int n   = blockIdx.x * PPB + p;

    // ---- stage tiles (each pixel's 64 threads; coalesced 512B per warp) ----
#pragma unroll
    for (int i = 0; i < 16; ++i) {
        int idx = q + i * 64;            // 1024 float4
        int k   = idx >> 4;
        int d4  = idx & 15;
        ts[p][tsw(k, d4)] = tg[((size_t)k * Nv + n) * D4v + d4];
    }
#pragma unroll
    for (int i = 0; i < 4; ++i) {
        int idx = q + i * 64;            // 256 float4
        int b   = idx >> 4;
        int d4  = idx & 15;
        xs[p][xsw(b, d4)] = xg[((size_t)b * Nv + n) * D4v + d4];
    }
    if (tid < Kv) clsf[tid] = (float)tcls[tid];
    if (q < Bv) {
        cnt[p][q]     = 0;
        refined[p][q] = 0xFFFFFFFFFFFFFFFFULL;
    }
    __syncthreads();

    // ---- norms: ||t_k||^2 (one row per thread), ||x_b||^2 (q<16) ----
    {
        float s0 = 0.f, s1 = 0.f, s2 = 0.f, s3 = 0.f;
#pragma unroll
        for (int d4 = 0; d4 < D4v; ++d4) {
            float4 v = ts[p][tsw(q, d4)];
            s0 = fmaf(v.x, v.x, s0); s1 = fmaf(v.y, v.y, s1);
            s2 = fmaf(v.z, v.z, s2); s3 = fmaf(v.w, v.w, s3);
        }
        t2s[p][q] = (s0 + s1) + (s2 + s3);
    }
    if (q < Bv) {
        float s0 = 0.f, s1 = 0.f, s2 = 0.f, s3 = 0.f;
#pragma unroll
        for (int d4 = 0; d4 < D4v; ++d4) {
            float4 v = xs[p][xsw(q, d4)];
            s0 = fmaf(v.x, v.x, s0); s1 = fmaf(v.y, v.y, s1);
            s2 = fmaf(v.z, v.z, s2); s3 = fmaf(v.w, v.w, s3);
        }
        x2s[p][q] = (s0 + s1) + (s2 + s3);
    }
    __syncthreads();

    // ---- Phase A: 4x4 register-tile dot products, packed f32x2 over d ----
    // thread covers b in {c, c+4, c+8, c+12}, k in {r, r+16, r+32, r+48}
    // acc2[i][j] = (sum over even-d pairs, sum over odd-d pairs); no packing
    // MOVs: the float4 smem tiles ARE (d,d+1) pairs, read as ulonglong2.
    const int c = q & 3;
    const int r = q >> 2;

    ull acc2[4][4];
#pragma unroll
    for (int i = 0; i < 4; ++i)
#pragma unroll
        for (int j = 0; j < 4; ++j) acc2[i][j] = 0ULL;   // (0.f, 0.f)

#pragma unroll 4
    for (int d4 = 0; d4 < D4v; ++d4) {
        ulonglong2 xv[4], tv[4];
#pragma unroll
        for (int i = 0; i < 4; ++i)
            xv[i] = *reinterpret_cast<const ulonglong2*>(&xs[p][xsw(c + 4 * i, d4)]);
#pragma unroll
        for (int j = 0; j < 4; ++j)
            tv[j] = *reinterpret_cast<const ulonglong2*>(&ts[p][tsw(r + 16 * j, d4)]);
#pragma unroll
        for (int i = 0; i < 4; ++i)
#pragma unroll
            for (int j = 0; j < 4; ++j) {
                acc2[i][j] = f2_fma(xv[i].x, tv[j].x, acc2[i][j]);
                acc2[i][j] = f2_fma(xv[i].y, tv[j].y, acc2[i][j]);
            }
    }

    // distances; per-thread min+argmin over its 4 k's per b
    float df[4][4];
#pragma unroll
    for (int i = 0; i < 4; ++i) {
        const int   b   = c + 4 * i;
        const float bx2 = x2s[p][b];
        float bestv = FLT_MAX;
        int   bestk = Kv;
#pragma unroll
        for (int j = 0; j < 4; ++j) {
            const int k = r + 16 * j;
            float lo, hi;
            f2_unpack(acc2[i][j], lo, hi);
            const float dot = lo + hi;
            const float d = bx2 + t2s[p][k] - 2.0f * dot;
            df[i][j] = d;
            if (d < bestv) { bestv = d; bestk = k; }  // j asc => first-min
        }
        rv[p][b][r] = bestv;
        ri[p][b][r] = bestk;
    }
    __syncthreads();

    // ---- fp32 min + argmin per b (q<16) ----
    if (q < Bv) {
        float bestv = rv[p][q][0];
        int   bestk = ri[p][q][0];
#pragma unroll
        for (int t = 1; t < 16; ++t) {
            const float v = rv[p][q][t];
            const int   k = ri[p][q][t];
            if (v < bestv || (v == bestv && k < bestk)) { bestv = v; bestk = k; }
        }
        bestvs[p][q] = bestv;
        bestks[p][q] = bestk;
    }
    __syncthreads();

    // ---- near-tie candidate count per b ----
#pragma unroll
    for (int i = 0; i < 4; ++i) {
        const int b = c + 4 * i;
        const float lim = bestvs[p][b] + EPS;
        int local = 0;
#pragma unroll
        for (int j = 0; j < 4; ++j) local += (df[i][j] <= lim) ? 1 : 0;
        if (local) atomicAdd(&cnt[p][b], local);
    }
    __syncthreads();

    // ---- Phase B (RARE): exact fp64 refinement for contested b ----
#pragma unroll
    for (int i = 0; i < 4; ++i) {
        const int b = c + 4 * i;
        if (cnt[p][b] < 2) continue;                  // uncontested: skip fp64
        const float lim = bestvs[p][b] + EPS;
#pragma unroll
        for (int j = 0; j < 4; ++j) {
            if (df[i][j] > lim) continue;
            const int k = r + 16 * j;
            double dd = 0.0;
            for (int d4 = 0; d4 < D4v; ++d4) {
                const float4 xv = xs[p][xsw(b, d4)];
                const float4 tv = ts[p][tsw(k, d4)];
                const double e0 = (double)xv.x - (double)tv.x;
                const double e1 = (double)xv.y - (double)tv.y;
                const double e2 = (double)xv.z - (double)tv.z;
                const double e3 = (double)xv.w - (double)tv.w;
                dd = fma(e0, e0, dd);
                dd = fma(e1, e1, dd);
                dd = fma(e2, e2, dd);
                dd = fma(e3, e3, dd);
            }
            const float dfx = (float)dd;              // exact -> fp32
            const ull key = ((ull)__float_as_uint(dfx) << 6) | (ull)k;
            atomicMin(&refined[p][b], key);
        }
    }
    __syncthreads();

    // ---- outputs ----
    if (q < Bv) {
        float bestv;
        int   bestk;
        if (cnt[p][q] >= 2) {
            const ull key = refined[p][q];
            bestk = (int)(key & 63ULL);
            bestv = __uint_as_float((unsigned int)(key >> 6));
        } else {
            bestv = bestvs[p][q];
            bestk = bestks[p][q];
        }
        const size_t BN = (size_t)Bv * Nv;
        const size_t o  = (size_t)q * Nv + n;
        out[o]           = (bestv <= 0.5f) ? 1.0f : 0.0f;  // mask @ 0.5
        out[BN + o]      = (bestv <= 1.0f) ? 1.0f : 0.0f;  // mask @ 1.0
        out[2 * BN + o]  = bestv;                          // min_dists
        out[3 * BN + o]  = clsf[bestk];                    // pred_classes
    }
}

extern "C" void kernel_launch(void* const* d_in, const int* in_sizes, int n_in,
                              void* d_out, int out_size)
{
    const float4* frame = (const float4*)d_in[0];   // [16,16384,64] f32
    const float4* tmpl  = (const float4*)d_in[1];   // [64,16384,64] f32
    const int*    tcls  = (const int*)d_in[2];      // [64] int32
    float*        out   = (float*)d_out;

    osc_kernel<<<Nv / PPB, 64 * PPB>>>(frame, tmpl, tcls, out);
}